// round 1
// baseline (speedup 1.0000x reference)
#include <cuda_runtime.h>

// ---------------------------------------------------------------------------
// DMoN: GCNConv(128->16) + ReLU + Linear(16->16) + softmax
// N=100000 nodes, E=3.2M edges.
// Pipeline:
//   1. detect edge index dtype (int32 vs int64) at runtime
//   2. init deg=1 (self loop), agg=b1
//   3. h = x @ W1              (f32x2 packed FMA, W1 in smem)
//   4. deg scatter (red.global.add.f32)
//   5. dinv = rsqrt(deg)
//   6. edge scatter: agg[dst] += h[src] * dinv[src]*dinv[dst]  (red.v4.f32)
//   7. epilogue: a = relu(agg + h*dinv^2)  [self loop], softmax(a@Wp+bp)
// ---------------------------------------------------------------------------

#define FIN 128
#define HID 16
#define CLS 16
#define MAXN 100000

__device__ float g_deg[MAXN];          // degree, then dinv (in place)
__device__ float g_h[MAXN * HID];      // x @ W1
__device__ float g_agg[MAXN * HID];    // aggregated messages (init = b1)
__device__ int   g_is64;               // 1 if edge_index stored as int64

// ---------------------------------------------------------------------------
// dtype detection: int64 nonneg values < 2^31 -> every odd 32-bit word is 0.
// Sample 512 odd words across the first in_sizes[5] 32-bit words (valid region
// for either dtype). If all are zero -> int64.
// ---------------------------------------------------------------------------
__global__ void detect_kernel(const int* __restrict__ e32, int nwords32) {
    __shared__ int nonzero;
    if (threadIdx.x == 0) nonzero = 0;
    __syncthreads();
    long long stride = nwords32 / (long long)blockDim.x;
    if (stride < 2) stride = 2;
    long long idx = ((long long)threadIdx.x * stride) | 1;
    if (idx < (long long)nwords32 && e32[idx] != 0) nonzero = 1;
    __syncthreads();
    if (threadIdx.x == 0) g_is64 = (nonzero == 0) ? 1 : 0;
}

__device__ __forceinline__ int edge_at(const void* edges, long long i, int is64) {
    if (is64) return (int)((const long long*)edges)[i];
    return ((const int*)edges)[i];
}

// ---------------------------------------------------------------------------
// init: deg = 1 (self loop), agg row = b1
// ---------------------------------------------------------------------------
__global__ void __launch_bounds__(256) init_kernel(const float* __restrict__ b1, int n) {
    int i = blockIdx.x * blockDim.x + threadIdx.x;
    if (i >= n) return;
    g_deg[i] = 1.0f;
    float4 b0 = ((const float4*)b1)[0];
    float4 bb1 = ((const float4*)b1)[1];
    float4 b2 = ((const float4*)b1)[2];
    float4 b3 = ((const float4*)b1)[3];
    float4* a = (float4*)(g_agg + (size_t)i * HID);
    a[0] = b0; a[1] = bb1; a[2] = b2; a[3] = b3;
}

// ---------------------------------------------------------------------------
// transform: h = x @ W1  (per-thread row, packed f32x2 FMA, W1 in smem)
// ---------------------------------------------------------------------------
__device__ __forceinline__ unsigned long long pack2(float v) {
    unsigned long long r;
    asm("mov.b64 %0, {%1, %1};" : "=l"(r) : "r"(__float_as_uint(v)));
    return r;
}
__device__ __forceinline__ void fma2(unsigned long long& acc,
                                     unsigned long long a, unsigned long long b) {
    asm("fma.rn.f32x2 %0, %1, %2, %0;" : "+l"(acc) : "l"(a), "l"(b));
}

__global__ void __launch_bounds__(256) transform_kernel(
    const float* __restrict__ x, const float* __restrict__ W1, int n) {
    __shared__ float Ws[FIN * HID];  // 8 KB
    for (int i = threadIdx.x; i < FIN * HID; i += blockDim.x) Ws[i] = W1[i];
    __syncthreads();

    int node = blockIdx.x * blockDim.x + threadIdx.x;
    if (node >= n) return;

    const float4* xr = (const float4*)(x + (size_t)node * FIN);
    unsigned long long acc[8];
#pragma unroll
    for (int j = 0; j < 8; j++) acc[j] = 0ULL;

#pragma unroll 8
    for (int k4 = 0; k4 < FIN / 4; k4++) {
        float4 xv = xr[k4];
        {
            unsigned long long xp = pack2(xv.x);
            const unsigned long long* wr = (const unsigned long long*)(Ws + (k4 * 4 + 0) * HID);
#pragma unroll
            for (int j = 0; j < 8; j++) fma2(acc[j], xp, wr[j]);
        }
        {
            unsigned long long xp = pack2(xv.y);
            const unsigned long long* wr = (const unsigned long long*)(Ws + (k4 * 4 + 1) * HID);
#pragma unroll
            for (int j = 0; j < 8; j++) fma2(acc[j], xp, wr[j]);
        }
        {
            unsigned long long xp = pack2(xv.z);
            const unsigned long long* wr = (const unsigned long long*)(Ws + (k4 * 4 + 2) * HID);
#pragma unroll
            for (int j = 0; j < 8; j++) fma2(acc[j], xp, wr[j]);
        }
        {
            unsigned long long xp = pack2(xv.w);
            const unsigned long long* wr = (const unsigned long long*)(Ws + (k4 * 4 + 3) * HID);
#pragma unroll
            for (int j = 0; j < 8; j++) fma2(acc[j], xp, wr[j]);
        }
    }

    float hrow[16];
#pragma unroll
    for (int j = 0; j < 8; j++) {
        unsigned int lo, hi;
        asm("mov.b64 {%0, %1}, %2;" : "=r"(lo), "=r"(hi) : "l"(acc[j]));
        hrow[2 * j]     = __uint_as_float(lo);
        hrow[2 * j + 1] = __uint_as_float(hi);
    }
    float4* hout = (float4*)(g_h + (size_t)node * HID);
#pragma unroll
    for (int q = 0; q < 4; q++)
        hout[q] = make_float4(hrow[4 * q], hrow[4 * q + 1], hrow[4 * q + 2], hrow[4 * q + 3]);
}

// ---------------------------------------------------------------------------
// degree scatter: deg[dst] += 1
// ---------------------------------------------------------------------------
__global__ void __launch_bounds__(256) deg_kernel(const void* __restrict__ edges, int E) {
    int e = blockIdx.x * blockDim.x + threadIdx.x;
    if (e >= E) return;
    int is64 = g_is64;
    int d = edge_at(edges, (long long)E + e, is64);
    asm volatile("red.global.add.f32 [%0], %1;" :: "l"(&g_deg[d]), "f"(1.0f) : "memory");
}

// ---------------------------------------------------------------------------
// dinv = rsqrt(deg)   (deg >= 1 always: self loop)
// ---------------------------------------------------------------------------
__global__ void __launch_bounds__(256) rsqrt_kernel(int n) {
    int i = blockIdx.x * blockDim.x + threadIdx.x;
    if (i < n) g_deg[i] = rsqrtf(g_deg[i]);
}

// ---------------------------------------------------------------------------
// edge scatter: agg[dst] += h[src] * dinv[src]*dinv[dst]
// ---------------------------------------------------------------------------
__global__ void __launch_bounds__(256) scatter_kernel(const void* __restrict__ edges, int E) {
    int e = blockIdx.x * blockDim.x + threadIdx.x;
    if (e >= E) return;
    int is64 = g_is64;
    int s = edge_at(edges, e, is64);
    int d = edge_at(edges, (long long)E + e, is64);
    float norm = g_deg[s] * g_deg[d];
    const float4* hs = (const float4*)(g_h + (size_t)s * HID);
    float* ad = g_agg + (size_t)d * HID;
#pragma unroll
    for (int q = 0; q < 4; q++) {
        float4 v = hs[q];
        v.x *= norm; v.y *= norm; v.z *= norm; v.w *= norm;
        asm volatile("red.global.add.v4.f32 [%0], {%1, %2, %3, %4};"
                     :: "l"(ad + 4 * q), "f"(v.x), "f"(v.y), "f"(v.z), "f"(v.w)
                     : "memory");
    }
}

// ---------------------------------------------------------------------------
// epilogue: a = relu(agg + h*dinv^2), logits = a@Wp + bp, softmax, store
// ---------------------------------------------------------------------------
__global__ void __launch_bounds__(256) finalize_kernel(
    const float* __restrict__ Wp, const float* __restrict__ bp,
    float* __restrict__ out, int n) {
    __shared__ float Wps[HID * CLS];
    __shared__ float bps[CLS];
    for (int i = threadIdx.x; i < HID * CLS; i += blockDim.x) Wps[i] = Wp[i];
    if (threadIdx.x < CLS) bps[threadIdx.x] = bp[threadIdx.x];
    __syncthreads();

    int i = blockIdx.x * blockDim.x + threadIdx.x;
    if (i >= n) return;

    float di = g_deg[i];
    float sl = di * di;  // self-loop norm

    float a[HID];
    const float4* ag = (const float4*)(g_agg + (size_t)i * HID);
    const float4* hv = (const float4*)(g_h + (size_t)i * HID);
#pragma unroll
    for (int q = 0; q < 4; q++) {
        float4 av = ag[q];
        float4 hh = hv[q];
        a[4 * q + 0] = fmaxf(fmaf(hh.x, sl, av.x), 0.0f);
        a[4 * q + 1] = fmaxf(fmaf(hh.y, sl, av.y), 0.0f);
        a[4 * q + 2] = fmaxf(fmaf(hh.z, sl, av.z), 0.0f);
        a[4 * q + 3] = fmaxf(fmaf(hh.w, sl, av.w), 0.0f);
    }

    float lg[CLS];
#pragma unroll
    for (int c = 0; c < CLS; c++) lg[c] = bps[c];
#pragma unroll
    for (int j = 0; j < HID; j++) {
        float aj = a[j];
#pragma unroll
        for (int c = 0; c < CLS; c++) lg[c] = fmaf(aj, Wps[j * CLS + c], lg[c]);
    }

    float m = lg[0];
#pragma unroll
    for (int c = 1; c < CLS; c++) m = fmaxf(m, lg[c]);
    float ssum = 0.0f;
#pragma unroll
    for (int c = 0; c < CLS; c++) { lg[c] = __expf(lg[c] - m); ssum += lg[c]; }
    float inv = 1.0f / ssum;
#pragma unroll
    for (int c = 0; c < CLS; c++) lg[c] *= inv;

    float4* o = (float4*)(out + (size_t)i * CLS);
#pragma unroll
    for (int q = 0; q < 4; q++)
        o[q] = make_float4(lg[4 * q], lg[4 * q + 1], lg[4 * q + 2], lg[4 * q + 3]);
}

// ---------------------------------------------------------------------------
// launch
// inputs: x[N*128] f32, W1[128*16] f32, b1[16] f32, Wp[16*16] f32, bp[16] f32,
//         edge_index[2*E] int32 or int64
// ---------------------------------------------------------------------------
extern "C" void kernel_launch(void* const* d_in, const int* in_sizes, int n_in,
                              void* d_out, int out_size) {
    const float* x  = (const float*)d_in[0];
    const float* W1 = (const float*)d_in[1];
    const float* b1 = (const float*)d_in[2];
    const float* Wp = (const float*)d_in[3];
    const float* bp = (const float*)d_in[4];
    const void*  edges = d_in[5];

    int n = in_sizes[0] / FIN;       // 100000
    int E = in_sizes[5] / 2;         // 3200000 (element count / 2, any dtype)

    int nb = (n + 255) / 256;
    int eb = (E + 255) / 256;

    detect_kernel<<<1, 512>>>((const int*)edges, in_sizes[5]);
    init_kernel<<<nb, 256>>>(b1, n);
    transform_kernel<<<nb, 256>>>(x, W1, n);
    deg_kernel<<<eb, 256>>>(edges, E);
    rsqrt_kernel<<<nb, 256>>>(n);
    scatter_kernel<<<eb, 256>>>(edges, E);
    finalize_kernel<<<nb, 256>>>(Wp, bp, (float*)d_out, n);
}

// round 2
// speedup vs baseline: 1.4055x; 1.4055x over previous
#include <cuda_runtime.h>

// ---------------------------------------------------------------------------
// DMoN: GCNConv(128->16) + ReLU + Linear(16->16) + softmax
// N=100000 nodes, E=3.2M edges.
// R2: 4-threads-per-edge scatter (4x fewer L1tex wavefronts),
//     fused transform||deg kernel, fused detect+init, vectorized index loads.
// ---------------------------------------------------------------------------

#define FIN 128
#define HID 16
#define CLS 16
#define MAXN 100000

__device__ float g_deg[MAXN];          // degree, then dinv (in place)
__device__ float g_h[MAXN * HID];      // x @ W1
__device__ float g_agg[MAXN * HID];    // aggregated messages (init = b1)
__device__ int   g_is64;               // 1 if edge_index stored as int64

__device__ __forceinline__ int edge_at(const void* edges, long long i, int is64) {
    if (is64) return (int)((const long long*)edges)[i];
    return ((const int*)edges)[i];
}

// ---------------------------------------------------------------------------
// init + dtype detect (block 0): deg = 1 (self loop), agg row = b1
// int64 nonneg < 2^31 -> every odd 32-bit word is 0; 256 samples.
// ---------------------------------------------------------------------------
__global__ void __launch_bounds__(256) init_detect_kernel(
    const float* __restrict__ b1, int n,
    const int* __restrict__ e32, int nwords32) {
    if (blockIdx.x == 0) {
        __shared__ int nonzero;
        if (threadIdx.x == 0) nonzero = 0;
        __syncthreads();
        long long stride = nwords32 / (long long)blockDim.x;
        if (stride < 2) stride = 2;
        long long idx = ((long long)threadIdx.x * stride) | 1;
        if (idx < (long long)nwords32 && e32[idx] != 0) nonzero = 1;
        __syncthreads();
        if (threadIdx.x == 0) g_is64 = (nonzero == 0) ? 1 : 0;
    }
    int i = blockIdx.x * blockDim.x + threadIdx.x;
    if (i >= n) return;
    g_deg[i] = 1.0f;
    float4 c0 = ((const float4*)b1)[0];
    float4 c1 = ((const float4*)b1)[1];
    float4 c2 = ((const float4*)b1)[2];
    float4 c3 = ((const float4*)b1)[3];
    float4* a = (float4*)(g_agg + (size_t)i * HID);
    a[0] = c0; a[1] = c1; a[2] = c2; a[3] = c3;
}

// ---------------------------------------------------------------------------
// packed f32x2 FMA helpers
// ---------------------------------------------------------------------------
__device__ __forceinline__ unsigned long long pack2(float v) {
    unsigned long long r;
    asm("mov.b64 %0, {%1, %1};" : "=l"(r) : "r"(__float_as_uint(v)));
    return r;
}
__device__ __forceinline__ void fma2(unsigned long long& acc,
                                     unsigned long long a, unsigned long long b) {
    asm("fma.rn.f32x2 %0, %1, %2, %0;" : "+l"(acc) : "l"(a), "l"(b));
}

// ---------------------------------------------------------------------------
// fused kernel: blocks [0, nbT) do h = x @ W1; blocks [nbT, ...) do degree
// scatter (4 edges per thread, vectorized index loads).
// ---------------------------------------------------------------------------
#define DEG_EPT 4  // edges per thread in deg branch

__global__ void __launch_bounds__(256) transform_deg_kernel(
    const float* __restrict__ x, const float* __restrict__ W1,
    const void* __restrict__ edges, int n, int E, int nbT) {
    if (blockIdx.x < nbT) {
        // ---- transform branch ----
        __shared__ float Ws[FIN * HID];  // 8 KB
        for (int i = threadIdx.x; i < FIN * HID; i += blockDim.x) Ws[i] = W1[i];
        __syncthreads();

        int node = blockIdx.x * blockDim.x + threadIdx.x;
        if (node >= n) return;

        const float4* xr = (const float4*)(x + (size_t)node * FIN);
        unsigned long long acc[8];
#pragma unroll
        for (int j = 0; j < 8; j++) acc[j] = 0ULL;

#pragma unroll 8
        for (int k4 = 0; k4 < FIN / 4; k4++) {
            float4 xv = xr[k4];
#pragma unroll
            for (int sub = 0; sub < 4; sub++) {
                float xs = (sub == 0) ? xv.x : (sub == 1) ? xv.y : (sub == 2) ? xv.z : xv.w;
                unsigned long long xp = pack2(xs);
                const unsigned long long* wr =
                    (const unsigned long long*)(Ws + (k4 * 4 + sub) * HID);
#pragma unroll
                for (int j = 0; j < 8; j++) fma2(acc[j], xp, wr[j]);
            }
        }

        float hrow[16];
#pragma unroll
        for (int j = 0; j < 8; j++) {
            unsigned int lo, hi;
            asm("mov.b64 {%0, %1}, %2;" : "=r"(lo), "=r"(hi) : "l"(acc[j]));
            hrow[2 * j]     = __uint_as_float(lo);
            hrow[2 * j + 1] = __uint_as_float(hi);
        }
        float4* hout = (float4*)(g_h + (size_t)node * HID);
#pragma unroll
        for (int q = 0; q < 4; q++)
            hout[q] = make_float4(hrow[4 * q], hrow[4 * q + 1],
                                  hrow[4 * q + 2], hrow[4 * q + 3]);
    } else {
        // ---- degree branch: deg[dst] += 1, 4 edges/thread ----
        int is64 = g_is64;
        long long t = (long long)(blockIdx.x - nbT) * blockDim.x + threadIdx.x;
        long long base = t * DEG_EPT;
        if (base >= E) return;
        int dd[DEG_EPT];
        if (base + DEG_EPT <= E) {
            if (is64) {
                const longlong2* p =
                    (const longlong2*)((const long long*)edges + E + base);
                longlong2 a = p[0], b = p[1];
                dd[0] = (int)a.x; dd[1] = (int)a.y; dd[2] = (int)b.x; dd[3] = (int)b.y;
            } else {
                int4 a = *(const int4*)((const int*)edges + E + base);
                dd[0] = a.x; dd[1] = a.y; dd[2] = a.z; dd[3] = a.w;
            }
#pragma unroll
            for (int k = 0; k < DEG_EPT; k++)
                asm volatile("red.global.add.f32 [%0], %1;"
                             :: "l"(&g_deg[dd[k]]), "f"(1.0f) : "memory");
        } else {
            for (long long e = base; e < E; e++) {
                int d = edge_at(edges, (long long)E + e, is64);
                asm volatile("red.global.add.f32 [%0], %1;"
                             :: "l"(&g_deg[d]), "f"(1.0f) : "memory");
            }
        }
    }
}

// ---------------------------------------------------------------------------
// dinv = rsqrt(deg)   (deg >= 1 always: self loop)
// ---------------------------------------------------------------------------
__global__ void __launch_bounds__(256) rsqrt_kernel(int n) {
    int i = blockIdx.x * blockDim.x + threadIdx.x;
    if (i < n) g_deg[i] = rsqrtf(g_deg[i]);
}

// ---------------------------------------------------------------------------
// edge scatter: agg[dst] += h[src] * dinv[src]*dinv[dst]
// 4 threads per edge: thread handles quarter q of the 16-float row.
// A warp covers 8 edges -> ~1 L1tex wavefront per edge for gather/red.
// ---------------------------------------------------------------------------
__global__ void __launch_bounds__(256) scatter_kernel(const void* __restrict__ edges, int E) {
    long long t = (long long)blockIdx.x * blockDim.x + threadIdx.x;
    long long e = t >> 2;
    int q = (int)(t & 3);
    if (e >= E) return;
    int is64 = g_is64;
    int s = edge_at(edges, e, is64);
    int d = edge_at(edges, (long long)E + e, is64);
    float norm = g_deg[s] * g_deg[d];
    float4 v = ((const float4*)(g_h + (size_t)s * HID))[q];
    v.x *= norm; v.y *= norm; v.z *= norm; v.w *= norm;
    float* ad = g_agg + (size_t)d * HID + 4 * q;
    asm volatile("red.global.add.v4.f32 [%0], {%1, %2, %3, %4};"
                 :: "l"(ad), "f"(v.x), "f"(v.y), "f"(v.z), "f"(v.w)
                 : "memory");
}

// ---------------------------------------------------------------------------
// epilogue: a = relu(agg + h*dinv^2), logits = a@Wp + bp, softmax, store
// ---------------------------------------------------------------------------
__global__ void __launch_bounds__(256) finalize_kernel(
    const float* __restrict__ Wp, const float* __restrict__ bp,
    float* __restrict__ out, int n) {
    __shared__ float Wps[HID * CLS];
    __shared__ float bps[CLS];
    for (int i = threadIdx.x; i < HID * CLS; i += blockDim.x) Wps[i] = Wp[i];
    if (threadIdx.x < CLS) bps[threadIdx.x] = bp[threadIdx.x];
    __syncthreads();

    int i = blockIdx.x * blockDim.x + threadIdx.x;
    if (i >= n) return;

    float di = g_deg[i];
    float sl = di * di;  // self-loop norm

    float a[HID];
    const float4* ag = (const float4*)(g_agg + (size_t)i * HID);
    const float4* hv = (const float4*)(g_h + (size_t)i * HID);
#pragma unroll
    for (int q = 0; q < 4; q++) {
        float4 av = ag[q];
        float4 hh = hv[q];
        a[4 * q + 0] = fmaxf(fmaf(hh.x, sl, av.x), 0.0f);
        a[4 * q + 1] = fmaxf(fmaf(hh.y, sl, av.y), 0.0f);
        a[4 * q + 2] = fmaxf(fmaf(hh.z, sl, av.z), 0.0f);
        a[4 * q + 3] = fmaxf(fmaf(hh.w, sl, av.w), 0.0f);
    }

    float lg[CLS];
#pragma unroll
    for (int c = 0; c < CLS; c++) lg[c] = bps[c];
#pragma unroll
    for (int j = 0; j < HID; j++) {
        float aj = a[j];
#pragma unroll
        for (int c = 0; c < CLS; c++) lg[c] = fmaf(aj, Wps[j * CLS + c], lg[c]);
    }

    float m = lg[0];
#pragma unroll
    for (int c = 1; c < CLS; c++) m = fmaxf(m, lg[c]);
    float ssum = 0.0f;
#pragma unroll
    for (int c = 0; c < CLS; c++) { lg[c] = __expf(lg[c] - m); ssum += lg[c]; }
    float inv = 1.0f / ssum;
#pragma unroll
    for (int c = 0; c < CLS; c++) lg[c] *= inv;

    float4* o = (float4*)(out + (size_t)i * CLS);
#pragma unroll
    for (int q = 0; q < 4; q++)
        o[q] = make_float4(lg[4 * q], lg[4 * q + 1], lg[4 * q + 2], lg[4 * q + 3]);
}

// ---------------------------------------------------------------------------
// launch
// ---------------------------------------------------------------------------
extern "C" void kernel_launch(void* const* d_in, const int* in_sizes, int n_in,
                              void* d_out, int out_size) {
    const float* x  = (const float*)d_in[0];
    const float* W1 = (const float*)d_in[1];
    const float* b1 = (const float*)d_in[2];
    const float* Wp = (const float*)d_in[3];
    const float* bp = (const float*)d_in[4];
    const void*  edges = d_in[5];

    int n = in_sizes[0] / FIN;       // 100000
    int E = in_sizes[5] / 2;         // 3200000

    int nb  = (n + 255) / 256;
    int nbT = nb;
    int degBlocks = (E + 256 * DEG_EPT - 1) / (256 * DEG_EPT);
    long long scatterThreads = 4LL * E;
    int sb = (int)((scatterThreads + 255) / 256);

    init_detect_kernel<<<nb, 256>>>(b1, n, (const int*)edges, in_sizes[5]);
    transform_deg_kernel<<<nbT + degBlocks, 256>>>(x, W1, edges, n, E, nbT);
    rsqrt_kernel<<<nb, 256>>>(n);
    scatter_kernel<<<sb, 256>>>(edges, E);
    finalize_kernel<<<nb, 256>>>(Wp, bp, (float*)d_out, n);
}

// round 3
// speedup vs baseline: 1.6793x; 1.1948x over previous
#include <cuda_runtime.h>

// ---------------------------------------------------------------------------
// DMoN: GCNConv(128->16) + ReLU + Linear(16->16) + softmax
// N=100000 nodes, E=3.2M edges.
// R3: normalization factored out of the edge loop.
//   h_s[i]   = (x@W1)[i] * dinv[i]           (per node)
//   agg[d]  += h_s[s]                        (per edge: gather 16B + RED 16B only)
//   out      = softmax(relu(dinv*(agg + h_s) + b1) @ Wp + bp)
// ---------------------------------------------------------------------------

#define FIN 128
#define HID 16
#define CLS 16
#define MAXN 100000

__device__ float g_deg[MAXN];          // degree, then dinv (in place)
__device__ float g_h[MAXN * HID];      // x @ W1, then pre-scaled by dinv
__device__ float g_agg[MAXN * HID];    // aggregated messages (init = 0)
__device__ int   g_is64;               // 1 if edge_index stored as int64

__device__ __forceinline__ int edge_at(const void* edges, long long i, int is64) {
    if (is64) return (int)((const long long*)edges)[i];
    return ((const int*)edges)[i];
}

// ---------------------------------------------------------------------------
// init + dtype detect (block 0): deg = 1 (self loop), agg row = 0
// int64 nonneg < 2^31 -> every odd 32-bit word is 0; 256 samples.
// ---------------------------------------------------------------------------
__global__ void __launch_bounds__(256) init_detect_kernel(
    int n, const int* __restrict__ e32, int nwords32) {
    if (blockIdx.x == 0) {
        __shared__ int nonzero;
        if (threadIdx.x == 0) nonzero = 0;
        __syncthreads();
        long long stride = nwords32 / (long long)blockDim.x;
        if (stride < 2) stride = 2;
        long long idx = ((long long)threadIdx.x * stride) | 1;
        if (idx < (long long)nwords32 && e32[idx] != 0) nonzero = 1;
        __syncthreads();
        if (threadIdx.x == 0) g_is64 = (nonzero == 0) ? 1 : 0;
    }
    int i = blockIdx.x * blockDim.x + threadIdx.x;
    if (i >= n) return;
    g_deg[i] = 1.0f;
    float4 z = make_float4(0.f, 0.f, 0.f, 0.f);
    float4* a = (float4*)(g_agg + (size_t)i * HID);
    a[0] = z; a[1] = z; a[2] = z; a[3] = z;
}

// ---------------------------------------------------------------------------
// packed f32x2 FMA helpers
// ---------------------------------------------------------------------------
__device__ __forceinline__ unsigned long long pack2(float v) {
    unsigned long long r;
    asm("mov.b64 %0, {%1, %1};" : "=l"(r) : "r"(__float_as_uint(v)));
    return r;
}
__device__ __forceinline__ void fma2(unsigned long long& acc,
                                     unsigned long long a, unsigned long long b) {
    asm("fma.rn.f32x2 %0, %1, %2, %0;" : "+l"(acc) : "l"(a), "l"(b));
}

// ---------------------------------------------------------------------------
// fused kernel: blocks [0, nbT) do h = x @ W1; blocks [nbT, ...) do degree
// scatter (4 edges per thread, vectorized index loads).
// ---------------------------------------------------------------------------
#define DEG_EPT 4

__global__ void __launch_bounds__(256) transform_deg_kernel(
    const float* __restrict__ x, const float* __restrict__ W1,
    const void* __restrict__ edges, int n, int E, int nbT) {
    if (blockIdx.x < nbT) {
        // ---- transform branch ----
        __shared__ float Ws[FIN * HID];  // 8 KB
        for (int i = threadIdx.x; i < FIN * HID; i += blockDim.x) Ws[i] = W1[i];
        __syncthreads();

        int node = blockIdx.x * blockDim.x + threadIdx.x;
        if (node >= n) return;

        const float4* xr = (const float4*)(x + (size_t)node * FIN);
        unsigned long long acc[8];
#pragma unroll
        for (int j = 0; j < 8; j++) acc[j] = 0ULL;

#pragma unroll 8
        for (int k4 = 0; k4 < FIN / 4; k4++) {
            float4 xv = xr[k4];
#pragma unroll
            for (int sub = 0; sub < 4; sub++) {
                float xs = (sub == 0) ? xv.x : (sub == 1) ? xv.y : (sub == 2) ? xv.z : xv.w;
                unsigned long long xp = pack2(xs);
                const unsigned long long* wr =
                    (const unsigned long long*)(Ws + (k4 * 4 + sub) * HID);
#pragma unroll
                for (int j = 0; j < 8; j++) fma2(acc[j], xp, wr[j]);
            }
        }

        float hrow[16];
#pragma unroll
        for (int j = 0; j < 8; j++) {
            unsigned int lo, hi;
            asm("mov.b64 {%0, %1}, %2;" : "=r"(lo), "=r"(hi) : "l"(acc[j]));
            hrow[2 * j]     = __uint_as_float(lo);
            hrow[2 * j + 1] = __uint_as_float(hi);
        }
        float4* hout = (float4*)(g_h + (size_t)node * HID);
#pragma unroll
        for (int q = 0; q < 4; q++)
            hout[q] = make_float4(hrow[4 * q], hrow[4 * q + 1],
                                  hrow[4 * q + 2], hrow[4 * q + 3]);
    } else {
        // ---- degree branch: deg[dst] += 1, 4 edges/thread ----
        int is64 = g_is64;
        long long t = (long long)(blockIdx.x - nbT) * blockDim.x + threadIdx.x;
        long long base = t * DEG_EPT;
        if (base >= E) return;
        int dd[DEG_EPT];
        if (base + DEG_EPT <= E) {
            if (is64) {
                const longlong2* p =
                    (const longlong2*)((const long long*)edges + E + base);
                longlong2 a = p[0], b = p[1];
                dd[0] = (int)a.x; dd[1] = (int)a.y; dd[2] = (int)b.x; dd[3] = (int)b.y;
            } else {
                int4 a = *(const int4*)((const int*)edges + E + base);
                dd[0] = a.x; dd[1] = a.y; dd[2] = a.z; dd[3] = a.w;
            }
#pragma unroll
            for (int k = 0; k < DEG_EPT; k++)
                asm volatile("red.global.add.f32 [%0], %1;"
                             :: "l"(&g_deg[dd[k]]), "f"(1.0f) : "memory");
        } else {
            for (long long e = base; e < E; e++) {
                int d = edge_at(edges, (long long)E + e, is64);
                asm volatile("red.global.add.f32 [%0], %1;"
                             :: "l"(&g_deg[d]), "f"(1.0f) : "memory");
            }
        }
    }
}

// ---------------------------------------------------------------------------
// dinv = rsqrt(deg); h[i] *= dinv[i]   (pre-scale source side)
// ---------------------------------------------------------------------------
__global__ void __launch_bounds__(256) rsqrt_scale_kernel(int n) {
    int i = blockIdx.x * blockDim.x + threadIdx.x;
    if (i >= n) return;
    float dinv = rsqrtf(g_deg[i]);
    g_deg[i] = dinv;
    float4* h = (float4*)(g_h + (size_t)i * HID);
#pragma unroll
    for (int q = 0; q < 4; q++) {
        float4 v = h[q];
        v.x *= dinv; v.y *= dinv; v.z *= dinv; v.w *= dinv;
        h[q] = v;
    }
}

// ---------------------------------------------------------------------------
// edge scatter: agg[dst] += h_s[src]
// 4 threads per edge (quarter rows). No per-edge normalization loads.
// ---------------------------------------------------------------------------
__global__ void __launch_bounds__(256) scatter_kernel(const void* __restrict__ edges, int E) {
    long long t = (long long)blockIdx.x * blockDim.x + threadIdx.x;
    long long e = t >> 2;
    int q = (int)(t & 3);
    if (e >= E) return;
    int is64 = g_is64;
    int s = edge_at(edges, e, is64);
    int d = edge_at(edges, (long long)E + e, is64);
    float4 v = ((const float4*)(g_h + (size_t)s * HID))[q];
    float* ad = g_agg + (size_t)d * HID + 4 * q;
    asm volatile("red.global.add.v4.f32 [%0], {%1, %2, %3, %4};"
                 :: "l"(ad), "f"(v.x), "f"(v.y), "f"(v.z), "f"(v.w)
                 : "memory");
}

// ---------------------------------------------------------------------------
// epilogue: a = relu(dinv*(agg + h_s) + b1), logits = a@Wp+bp, softmax
// (self loop h*dinv^2 == h_s*dinv is included via the +h_s term)
// ---------------------------------------------------------------------------
__global__ void __launch_bounds__(256) finalize_kernel(
    const float* __restrict__ b1, const float* __restrict__ Wp,
    const float* __restrict__ bp, float* __restrict__ out, int n) {
    __shared__ float Wps[HID * CLS];
    __shared__ float bps[CLS];
    __shared__ float b1s[HID];
    for (int i = threadIdx.x; i < HID * CLS; i += blockDim.x) Wps[i] = Wp[i];
    if (threadIdx.x < CLS) bps[threadIdx.x] = bp[threadIdx.x];
    if (threadIdx.x < HID) b1s[threadIdx.x] = b1[threadIdx.x];
    __syncthreads();

    int i = blockIdx.x * blockDim.x + threadIdx.x;
    if (i >= n) return;

    float dinv = g_deg[i];

    float a[HID];
    const float4* ag = (const float4*)(g_agg + (size_t)i * HID);
    const float4* hv = (const float4*)(g_h + (size_t)i * HID);
#pragma unroll
    for (int q = 0; q < 4; q++) {
        float4 av = ag[q];
        float4 hh = hv[q];
        a[4 * q + 0] = fmaxf(fmaf(av.x + hh.x, dinv, b1s[4 * q + 0]), 0.0f);
        a[4 * q + 1] = fmaxf(fmaf(av.y + hh.y, dinv, b1s[4 * q + 1]), 0.0f);
        a[4 * q + 2] = fmaxf(fmaf(av.z + hh.z, dinv, b1s[4 * q + 2]), 0.0f);
        a[4 * q + 3] = fmaxf(fmaf(av.w + hh.w, dinv, b1s[4 * q + 3]), 0.0f);
    }

    float lg[CLS];
#pragma unroll
    for (int c = 0; c < CLS; c++) lg[c] = bps[c];
#pragma unroll
    for (int j = 0; j < HID; j++) {
        float aj = a[j];
#pragma unroll
        for (int c = 0; c < CLS; c++) lg[c] = fmaf(aj, Wps[j * CLS + c], lg[c]);
    }

    float m = lg[0];
#pragma unroll
    for (int c = 1; c < CLS; c++) m = fmaxf(m, lg[c]);
    float ssum = 0.0f;
#pragma unroll
    for (int c = 0; c < CLS; c++) { lg[c] = __expf(lg[c] - m); ssum += lg[c]; }
    float inv = 1.0f / ssum;
#pragma unroll
    for (int c = 0; c < CLS; c++) lg[c] *= inv;

    float4* o = (float4*)(out + (size_t)i * CLS);
#pragma unroll
    for (int q = 0; q < 4; q++)
        o[q] = make_float4(lg[4 * q], lg[4 * q + 1], lg[4 * q + 2], lg[4 * q + 3]);
}

// ---------------------------------------------------------------------------
// launch
// ---------------------------------------------------------------------------
extern "C" void kernel_launch(void* const* d_in, const int* in_sizes, int n_in,
                              void* d_out, int out_size) {
    const float* x  = (const float*)d_in[0];
    const float* W1 = (const float*)d_in[1];
    const float* b1 = (const float*)d_in[2];
    const float* Wp = (const float*)d_in[3];
    const float* bp = (const float*)d_in[4];
    const void*  edges = d_in[5];

    int n = in_sizes[0] / FIN;       // 100000
    int E = in_sizes[5] / 2;         // 3200000

    int nb  = (n + 255) / 256;
    int nbT = nb;
    int degBlocks = (E + 256 * DEG_EPT - 1) / (256 * DEG_EPT);
    long long scatterThreads = 4LL * E;
    int sb = (int)((scatterThreads + 255) / 256);

    init_detect_kernel<<<nb, 256>>>(n, (const int*)edges, in_sizes[5]);
    transform_deg_kernel<<<nbT + degBlocks, 256>>>(x, W1, edges, n, E, nbT);
    rsqrt_scale_kernel<<<nb, 256>>>(n);
    scatter_kernel<<<sb, 256>>>(edges, E);
    finalize_kernel<<<nb, 256>>>(b1, Wp, bp, (float*)d_out, n);
}

// round 6
// speedup vs baseline: 1.6865x; 1.0043x over previous
#include <cuda_runtime.h>

// ---------------------------------------------------------------------------
// DMoN: GCNConv(128->16) + ReLU + Linear(16->16) + softmax
// N=100000 nodes, E=3.2M edges.
// R6: proven R3 structure; scatter handles 2 far-apart quarters per thread
//     (grid-stride), 16B-aligned globals.
// ---------------------------------------------------------------------------

#define FIN 128
#define HID 16
#define CLS 16
#define MAXN 100000

__device__ __align__(16) float g_deg[MAXN];        // degree, then dinv (in place)
__device__ __align__(16) float g_h[MAXN * HID];    // x @ W1, then pre-scaled by dinv
__device__ __align__(16) float g_agg[MAXN * HID];  // aggregated messages (init = b1... = 0+b1)
__device__ int g_is64;                             // 1 if edge_index stored as int64

__device__ __forceinline__ int edge_at(const void* edges, long long i, int is64) {
    if (is64) return (int)((const long long*)edges)[i];
    return ((const int*)edges)[i];
}

// ---------------------------------------------------------------------------
// init + dtype detect (block 0): deg = 1 (self loop), agg row = 0
// int64 nonneg < 2^31 -> every odd 32-bit word is 0; 256 samples.
// (identical to R3 which passed)
// ---------------------------------------------------------------------------
__global__ void __launch_bounds__(256) init_detect_kernel(
    int n, const int* __restrict__ e32, int nwords32) {
    if (blockIdx.x == 0) {
        __shared__ int nonzero;
        if (threadIdx.x == 0) nonzero = 0;
        __syncthreads();
        long long stride = nwords32 / (long long)blockDim.x;
        if (stride < 2) stride = 2;
        long long idx = ((long long)threadIdx.x * stride) | 1;
        if (idx < (long long)nwords32 && e32[idx] != 0) nonzero = 1;
        __syncthreads();
        if (threadIdx.x == 0) g_is64 = (nonzero == 0) ? 1 : 0;
    }
    int i = blockIdx.x * blockDim.x + threadIdx.x;
    if (i >= n) return;
    g_deg[i] = 1.0f;
    float4 z = make_float4(0.f, 0.f, 0.f, 0.f);
    float4* a = (float4*)(g_agg + (size_t)i * HID);
    a[0] = z; a[1] = z; a[2] = z; a[3] = z;
}

// ---------------------------------------------------------------------------
// packed f32x2 FMA helpers
// ---------------------------------------------------------------------------
__device__ __forceinline__ unsigned long long pack2(float v) {
    unsigned long long r;
    asm("mov.b64 %0, {%1, %1};" : "=l"(r) : "r"(__float_as_uint(v)));
    return r;
}
__device__ __forceinline__ void fma2(unsigned long long& acc,
                                     unsigned long long a, unsigned long long b) {
    asm("fma.rn.f32x2 %0, %1, %2, %0;" : "+l"(acc) : "l"(a), "l"(b));
}

// ---------------------------------------------------------------------------
// fused: blocks [0,nbT) h = x @ W1 ; blocks [nbT,..) degree scatter
// (identical to R3 which passed)
// ---------------------------------------------------------------------------
#define DEG_EPT 4

__global__ void __launch_bounds__(256) transform_deg_kernel(
    const float* __restrict__ x, const float* __restrict__ W1,
    const void* __restrict__ edges, int n, int E, int nbT) {
    if (blockIdx.x < nbT) {
        __shared__ float Ws[FIN * HID];  // 8 KB
        for (int i = threadIdx.x; i < FIN * HID; i += blockDim.x) Ws[i] = W1[i];
        __syncthreads();

        int node = blockIdx.x * blockDim.x + threadIdx.x;
        if (node >= n) return;

        const float4* xr = (const float4*)(x + (size_t)node * FIN);
        unsigned long long acc[8];
#pragma unroll
        for (int j = 0; j < 8; j++) acc[j] = 0ULL;

#pragma unroll 8
        for (int k4 = 0; k4 < FIN / 4; k4++) {
            float4 xv = xr[k4];
#pragma unroll
            for (int sub = 0; sub < 4; sub++) {
                float xs = (sub == 0) ? xv.x : (sub == 1) ? xv.y : (sub == 2) ? xv.z : xv.w;
                unsigned long long xp = pack2(xs);
                const unsigned long long* wr =
                    (const unsigned long long*)(Ws + (k4 * 4 + sub) * HID);
#pragma unroll
                for (int j = 0; j < 8; j++) fma2(acc[j], xp, wr[j]);
            }
        }

        float hrow[16];
#pragma unroll
        for (int j = 0; j < 8; j++) {
            unsigned int lo, hi;
            asm("mov.b64 {%0, %1}, %2;" : "=r"(lo), "=r"(hi) : "l"(acc[j]));
            hrow[2 * j]     = __uint_as_float(lo);
            hrow[2 * j + 1] = __uint_as_float(hi);
        }
        float4* hout = (float4*)(g_h + (size_t)node * HID);
#pragma unroll
        for (int q = 0; q < 4; q++)
            hout[q] = make_float4(hrow[4 * q], hrow[4 * q + 1],
                                  hrow[4 * q + 2], hrow[4 * q + 3]);
    } else {
        int is64 = g_is64;
        long long t = (long long)(blockIdx.x - nbT) * blockDim.x + threadIdx.x;
        long long base = t * DEG_EPT;
        if (base >= E) return;
        if (base + DEG_EPT <= E) {
            int dd[DEG_EPT];
            if (is64) {
                const longlong2* p =
                    (const longlong2*)((const long long*)edges + E + base);
                longlong2 a = p[0], b = p[1];
                dd[0] = (int)a.x; dd[1] = (int)a.y; dd[2] = (int)b.x; dd[3] = (int)b.y;
            } else {
                int4 a = *(const int4*)((const int*)edges + E + base);
                dd[0] = a.x; dd[1] = a.y; dd[2] = a.z; dd[3] = a.w;
            }
#pragma unroll
            for (int k = 0; k < DEG_EPT; k++)
                asm volatile("red.global.add.f32 [%0], %1;"
                             :: "l"(&g_deg[dd[k]]), "f"(1.0f) : "memory");
        } else {
            for (long long e = base; e < E; e++) {
                int d = edge_at(edges, (long long)E + e, is64);
                asm volatile("red.global.add.f32 [%0], %1;"
                             :: "l"(&g_deg[d]), "f"(1.0f) : "memory");
            }
        }
    }
}

// ---------------------------------------------------------------------------
// dinv = rsqrt(deg); h[i] *= dinv (pre-scale source side)  [identical to R3]
// ---------------------------------------------------------------------------
__global__ void __launch_bounds__(256) rsqrt_scale_kernel(int n) {
    int i = blockIdx.x * blockDim.x + threadIdx.x;
    if (i >= n) return;
    float dinv = rsqrtf(g_deg[i]);
    g_deg[i] = dinv;
    float4* h = (float4*)(g_h + (size_t)i * HID);
#pragma unroll
    for (int q = 0; q < 4; q++) {
        float4 v = h[q];
        v.x *= dinv; v.y *= dinv; v.z *= dinv; v.w *= dinv;
        h[q] = v;
    }
}

// ---------------------------------------------------------------------------
// edge scatter: agg[dst] += h_s[src]
// R3 body, grid-stride: each thread handles quarters t and t + half.
// The two iterations touch far-apart edges (no provable adjacency).
// ---------------------------------------------------------------------------
__global__ void __launch_bounds__(256) scatter_kernel(const void* __restrict__ edges,
                                                      int E, long long half) {
    int is64 = g_is64;
    long long totalq = 4LL * E;
    long long t = (long long)blockIdx.x * blockDim.x + threadIdx.x;
#pragma unroll
    for (int it = 0; it < 2; it++) {
        if (t < totalq) {
            long long e = t >> 2;
            int q = (int)(t & 3);
            int s = edge_at(edges, e, is64);
            int d = edge_at(edges, (long long)E + e, is64);
            float4 v = ((const float4*)(g_h + (size_t)s * HID))[q];
            float* ad = g_agg + (size_t)d * HID + 4 * q;
            asm volatile("red.global.add.v4.f32 [%0], {%1, %2, %3, %4};"
                         :: "l"(ad), "f"(v.x), "f"(v.y), "f"(v.z), "f"(v.w)
                         : "memory");
        }
        t += half;
    }
}

// ---------------------------------------------------------------------------
// epilogue: a = relu(dinv*(agg + h_s) + b1), logits = a@Wp+bp, softmax
// (identical to R3)
// ---------------------------------------------------------------------------
__global__ void __launch_bounds__(256) finalize_kernel(
    const float* __restrict__ b1, const float* __restrict__ Wp,
    const float* __restrict__ bp, float* __restrict__ out, int n) {
    __shared__ float Wps[HID * CLS];
    __shared__ float bps[CLS];
    __shared__ float b1s[HID];
    for (int i = threadIdx.x; i < HID * CLS; i += blockDim.x) Wps[i] = Wp[i];
    if (threadIdx.x < CLS) bps[threadIdx.x] = bp[threadIdx.x];
    if (threadIdx.x < HID) b1s[threadIdx.x] = b1[threadIdx.x];
    __syncthreads();

    int i = blockIdx.x * blockDim.x + threadIdx.x;
    if (i >= n) return;

    float dinv = g_deg[i];

    float a[HID];
    const float4* ag = (const float4*)(g_agg + (size_t)i * HID);
    const float4* hv = (const float4*)(g_h + (size_t)i * HID);
#pragma unroll
    for (int q = 0; q < 4; q++) {
        float4 av = ag[q];
        float4 hh = hv[q];
        a[4 * q + 0] = fmaxf(fmaf(av.x + hh.x, dinv, b1s[4 * q + 0]), 0.0f);
        a[4 * q + 1] = fmaxf(fmaf(av.y + hh.y, dinv, b1s[4 * q + 1]), 0.0f);
        a[4 * q + 2] = fmaxf(fmaf(av.z + hh.z, dinv, b1s[4 * q + 2]), 0.0f);
        a[4 * q + 3] = fmaxf(fmaf(av.w + hh.w, dinv, b1s[4 * q + 3]), 0.0f);
    }

    float lg[CLS];
#pragma unroll
    for (int c = 0; c < CLS; c++) lg[c] = bps[c];
#pragma unroll
    for (int j = 0; j < HID; j++) {
        float aj = a[j];
#pragma unroll
        for (int c = 0; c < CLS; c++) lg[c] = fmaf(aj, Wps[j * CLS + c], lg[c]);
    }

    float m = lg[0];
#pragma unroll
    for (int c = 1; c < CLS; c++) m = fmaxf(m, lg[c]);
    float ssum = 0.0f;
#pragma unroll
    for (int c = 0; c < CLS; c++) { lg[c] = __expf(lg[c] - m); ssum += lg[c]; }
    float inv = 1.0f / ssum;
#pragma unroll
    for (int c = 0; c < CLS; c++) lg[c] *= inv;

    float4* o = (float4*)(out + (size_t)i * CLS);
#pragma unroll
    for (int q = 0; q < 4; q++)
        o[q] = make_float4(lg[4 * q], lg[4 * q + 1], lg[4 * q + 2], lg[4 * q + 3]);
}

// ---------------------------------------------------------------------------
// launch
// ---------------------------------------------------------------------------
extern "C" void kernel_launch(void* const* d_in, const int* in_sizes, int n_in,
                              void* d_out, int out_size) {
    const float* x  = (const float*)d_in[0];
    const float* W1 = (const float*)d_in[1];
    const float* b1 = (const float*)d_in[2];
    const float* Wp = (const float*)d_in[3];
    const float* bp = (const float*)d_in[4];
    const void*  edges = d_in[5];

    int n = in_sizes[0] / FIN;       // 100000
    int E = in_sizes[5] / 2;         // 3200000

    int nb  = (n + 255) / 256;
    int nbT = nb;
    int degBlocks = (E + 256 * DEG_EPT - 1) / (256 * DEG_EPT);

    long long totalq = 4LL * E;
    long long half = (totalq + 1) / 2;
    int sb = (int)((half + 255) / 256);

    init_detect_kernel<<<nb, 256>>>(n, (const int*)edges, in_sizes[5]);
    transform_deg_kernel<<<nbT + degBlocks, 256>>>(x, W1, edges, n, E, nbT);
    rsqrt_scale_kernel<<<nb, 256>>>(n);
    scatter_kernel<<<sb, 256>>>(edges, E, half);
    finalize_kernel<<<nb, 256>>>(b1, Wp, bp, (float*)d_out, n);
}